// round 1
// baseline (speedup 1.0000x reference)
#include <cuda_runtime.h>
#include <cstdint>

#define M_DIM   32
#define IN_DIM  4096
#define OUT_DIM 16384

#define O_TILE  64
#define KC      64
#define NC      (IN_DIM / KC)      // 64 k-chunks
#define QS_STRIDE 66               // conflict-free STS: bank = (2k+o) mod 32 covers all 32
#define XS_STRIDE 36               // multiple of 4 -> float4-aligned rows

__global__ __launch_bounds__(256, 2)
void qgemm_f32x2_kernel(const float* __restrict__ x,
                        const int*   __restrict__ wq,
                        const int*   __restrict__ zerop,
                        const float* __restrict__ scalep,
                        const float* __restrict__ bias,
                        float*       __restrict__ out)
{
    __shared__ float Qs[KC * QS_STRIDE];   // Qs[k][o], dequant-centered weights
    __shared__ float Xs[KC * XS_STRIDE];   // Xs[k][m]

    const int t  = threadIdx.x;
    const int ob = blockIdx.x * O_TILE;

    const int   zero  = zerop[0];
    const float scale = scalep[0];

    // ---- Q load mapping: row r = t/4, quad q4 = t%4; each thread loads 4x int4
    //      at k = q4*4 + i*16  (quad covers 64B contiguous -> coalesced)
    const int qr = t >> 2;       // 0..63  (o within tile)
    const int q4 = t & 3;
    const int* qptr = wq + (size_t)(ob + qr) * IN_DIM + q4 * 4;

    // ---- X load mapping: m = t/8, seg = t%8; each thread loads 8 floats (2x float4)
    const int xm = t >> 3;       // 0..31
    const int xs = t & 7;
    const float* xptr = x + (size_t)xm * IN_DIM + xs * 8;

    // ---- compute mapping: o pair = 2*to, m quad = 4*tm (tm uniform within a warp)
    const int to = t & 31;
    const int tm = t >> 5;

    int4   qreg[4];
    float4 xreg[2];

    // accumulators: acc[o_i][m_pair] packed f32x2
    unsigned long long acc[2][2];
    acc[0][0] = 0ull; acc[0][1] = 0ull; acc[1][0] = 0ull; acc[1][1] = 0ull;

    // prefetch chunk 0
#pragma unroll
    for (int i = 0; i < 4; i++) qreg[i] = *(const int4*)(qptr + i * 16);
    xreg[0] = *(const float4*)(xptr);
    xreg[1] = *(const float4*)(xptr + 4);

    for (int c = 0; c < NC; c++) {
        // ---- stage to smem (convert int code -> centered float)
#pragma unroll
        for (int i = 0; i < 4; i++) {
            const int kb = q4 * 4 + i * 16;
            Qs[(kb + 0) * QS_STRIDE + qr] = (float)(qreg[i].x - zero);
            Qs[(kb + 1) * QS_STRIDE + qr] = (float)(qreg[i].y - zero);
            Qs[(kb + 2) * QS_STRIDE + qr] = (float)(qreg[i].z - zero);
            Qs[(kb + 3) * QS_STRIDE + qr] = (float)(qreg[i].w - zero);
        }
        {
            const int kb = xs * 8;
            Xs[(kb + 0) * XS_STRIDE + xm] = xreg[0].x;
            Xs[(kb + 1) * XS_STRIDE + xm] = xreg[0].y;
            Xs[(kb + 2) * XS_STRIDE + xm] = xreg[0].z;
            Xs[(kb + 3) * XS_STRIDE + xm] = xreg[0].w;
            Xs[(kb + 4) * XS_STRIDE + xm] = xreg[1].x;
            Xs[(kb + 5) * XS_STRIDE + xm] = xreg[1].y;
            Xs[(kb + 6) * XS_STRIDE + xm] = xreg[1].z;
            Xs[(kb + 7) * XS_STRIDE + xm] = xreg[1].w;
        }
        __syncthreads();

        // ---- prefetch next chunk into regs (overlaps with compute below)
        if (c + 1 < NC) {
            qptr += KC;
            xptr += KC;
#pragma unroll
            for (int i = 0; i < 4; i++) qreg[i] = *(const int4*)(qptr + i * 16);
            xreg[0] = *(const float4*)(xptr);
            xreg[1] = *(const float4*)(xptr + 4);
        }

        // ---- compute: 2o x 4m micro-tile, packed f32x2 FMAs
#pragma unroll 16
        for (int kk = 0; kk < KC; kk++) {
            float2 qv = *(const float2*)(Qs + kk * QS_STRIDE + 2 * to);
            float4 xv = *(const float4*)(Xs + kk * XS_STRIDE + 4 * tm);

            unsigned long long q0, q1, x0, x1;
            asm("mov.b64 %0, {%1, %1};" : "=l"(q0) : "f"(qv.x));
            asm("mov.b64 %0, {%1, %1};" : "=l"(q1) : "f"(qv.y));
            asm("mov.b64 %0, {%1, %2};" : "=l"(x0) : "f"(xv.x), "f"(xv.y));
            asm("mov.b64 %0, {%1, %2};" : "=l"(x1) : "f"(xv.z), "f"(xv.w));

            asm("fma.rn.f32x2 %0, %1, %2, %0;" : "+l"(acc[0][0]) : "l"(q0), "l"(x0));
            asm("fma.rn.f32x2 %0, %1, %2, %0;" : "+l"(acc[0][1]) : "l"(q0), "l"(x1));
            asm("fma.rn.f32x2 %0, %1, %2, %0;" : "+l"(acc[1][0]) : "l"(q1), "l"(x0));
            asm("fma.rn.f32x2 %0, %1, %2, %0;" : "+l"(acc[1][1]) : "l"(q1), "l"(x1));
        }
        __syncthreads();
    }

    // ---- epilogue: y = scale*acc + bias
#pragma unroll
    for (int i = 0; i < 2; i++) {
        const int o = ob + 2 * to + i;
        const float b = bias[o];
#pragma unroll
        for (int p = 0; p < 2; p++) {
            float lo, hi;
            asm("mov.b64 {%0, %1}, %2;" : "=f"(lo), "=f"(hi) : "l"(acc[i][p]));
            const int m0 = 4 * tm + 2 * p;
            out[(size_t)(m0 + 0) * OUT_DIM + o] = fmaf(scale, lo, b);
            out[(size_t)(m0 + 1) * OUT_DIM + o] = fmaf(scale, hi, b);
        }
    }
}

extern "C" void kernel_launch(void* const* d_in, const int* in_sizes, int n_in,
                              void* d_out, int out_size)
{
    const float* x     = (const float*)d_in[0];
    const int*   wq    = (const int*)  d_in[1];
    const int*   zero  = (const int*)  d_in[2];
    const float* scale = (const float*)d_in[3];
    const float* bias  = (const float*)d_in[4];
    float*       out   = (float*)d_out;

    qgemm_f32x2_kernel<<<OUT_DIM / O_TILE, 256>>>(x, wq, zero, scale, bias, out);
}

// round 2
// speedup vs baseline: 1.3109x; 1.3109x over previous
#include <cuda_runtime.h>
#include <cstdint>

#define IN_DIM   4096
#define OUT_DIM  16384
#define MDIM     32

#define OTILE    512                 // outputs per CTA (2 per thread, 256 threads)
#define KSPLIT   512                 // K range per CTA
#define NSPLIT   (IN_DIM / KSPLIT)   // 8
#define KC       16                  // k chunk staged per double-buffer step
#define NCHUNK   (KSPLIT / KC)       // 32
#define QS_STRIDE 514                // floats per k-row (512 + 2 pad): STS conflict-free, LDS.64 8B-aligned
#define XS_STRIDE 36                 // floats per k-row (32 + 4 pad): 16B-aligned rows
#define QS_FLOATS (KC * QS_STRIDE)   // 8224
#define XS_FLOATS (KC * XS_STRIDE)   // 576
#define SMEM_BYTES ((2 * QS_FLOATS + 2 * XS_FLOATS) * 4)   // 70400 B

// split-K partials (written by main kernel, summed by reduce kernel)
__device__ float g_partial[NSPLIT][MDIM][OUT_DIM];

__device__ __forceinline__ void fma2(unsigned long long& a,
                                     unsigned long long b,
                                     unsigned long long c) {
    asm("fma.rn.f32x2 %0, %1, %2, %0;" : "+l"(a) : "l"(b), "l"(c));
}

__global__ __launch_bounds__(256, 2)
void qgemm_main(const float* __restrict__ x,
                const int*   __restrict__ wq,
                const int*   __restrict__ zerop)
{
    extern __shared__ float smem[];
    float* Qs = smem;                       // [2][KC][QS_STRIDE] centered weights
    float* Xs = smem + 2 * QS_FLOATS;       // [2][KC][XS_STRIDE]
    const uint32_t smem_u32 = (uint32_t)__cvta_generic_to_shared(smem);

    const int t  = threadIdx.x;
    const int ob = blockIdx.x * OTILE;
    const int ks = blockIdx.y * KSPLIT;
    const int zero = zerop[0];

    // ---- Q global-load map: 8 passes; pass p: row = (t>>2)+64p, 4 lanes cover 64B of the row
    const int qrow = t >> 2;                // 0..63
    const int qseg = t & 3;                 // int4 segment within the 16-int chunk row
    const int* qbase = wq + (size_t)(ob + qrow) * IN_DIM + ks + qseg * 4;

    // ---- X global-load map (t < 128): row m = t>>2 (0..31), 4 lanes cover 64B
    const int xm   = t >> 2;
    const int xseg = t & 3;
    const float* xbase = x + (size_t)xm * IN_DIM + ks + xseg * 4;

    int4   qreg[8];
    float4 xreg;

    unsigned long long acc[32];             // [o 0/1][m-pair 0..15]
#pragma unroll
    for (int i = 0; i < 32; i++) acc[i] = 0ull;

    // ---------------- staging helpers (inlined manually) ----------------
    // LDG chunk c
#define LDG_CHUNK(c)                                                          \
    do {                                                                      \
        _Pragma("unroll")                                                     \
        for (int p = 0; p < 8; p++)                                           \
            qreg[p] = *(const int4*)(qbase + (size_t)p * 64 * IN_DIM + (c) * KC); \
        if (t < 128) xreg = *(const float4*)(xbase + (c) * KC);               \
    } while (0)

    // STS chunk into buffer b (converts q -> centered float via IADD+I2F)
#define STS_CHUNK(b)                                                          \
    do {                                                                      \
        float* qdst = Qs + (b) * QS_FLOATS;                                   \
        _Pragma("unroll")                                                     \
        for (int p = 0; p < 8; p++) {                                         \
            const int oo = qrow + 64 * p;                                     \
            const int kb = qseg * 4;                                          \
            qdst[(kb + 0) * QS_STRIDE + oo] = (float)(qreg[p].x - zero);      \
            qdst[(kb + 1) * QS_STRIDE + oo] = (float)(qreg[p].y - zero);      \
            qdst[(kb + 2) * QS_STRIDE + oo] = (float)(qreg[p].z - zero);      \
            qdst[(kb + 3) * QS_STRIDE + oo] = (float)(qreg[p].w - zero);      \
        }                                                                     \
        if (t < 128) {                                                        \
            float* xdst = Xs + (b) * XS_FLOATS;                               \
            const int kb = xseg * 4;                                          \
            xdst[(kb + 0) * XS_STRIDE + xm] = xreg.x;                         \
            xdst[(kb + 1) * XS_STRIDE + xm] = xreg.y;                         \
            xdst[(kb + 2) * XS_STRIDE + xm] = xreg.z;                         \
            xdst[(kb + 3) * XS_STRIDE + xm] = xreg.w;                         \
        }                                                                     \
    } while (0)

    // ---------------- pipeline ----------------
    LDG_CHUNK(0);
    STS_CHUNK(0);
    __syncthreads();

    for (int c = 0; c < NCHUNK; c++) {
        const int b = c & 1;

        if (c + 1 < NCHUNK) LDG_CHUNK(c + 1);

        // ---- compute KC k's from buffer b
        const uint32_t qb = smem_u32 + (b * QS_FLOATS) * 4 + t * 8;
        const uint32_t xb = smem_u32 + (2 * QS_FLOATS + b * XS_FLOATS) * 4;
#pragma unroll
        for (int kk = 0; kk < KC; kk++) {
            float qf0, qf1;
            asm("ld.shared.v2.f32 {%0, %1}, [%2];"
                : "=f"(qf0), "=f"(qf1) : "r"(qb + kk * (QS_STRIDE * 4)));
            unsigned long long q0, q1;
            asm("mov.b64 %0, {%1, %1};" : "=l"(q0) : "f"(qf0));
            asm("mov.b64 %0, {%1, %1};" : "=l"(q1) : "f"(qf1));

            const uint32_t xrow = xb + kk * (XS_STRIDE * 4);
#pragma unroll
            for (int p = 0; p < 8; p++) {                // 2 m-pairs per load
                unsigned long long xa, xc;
                asm("ld.shared.v2.u64 {%0, %1}, [%2];"
                    : "=l"(xa), "=l"(xc) : "r"(xrow + p * 16));
                fma2(acc[2 * p + 0],      q0, xa);
                fma2(acc[2 * p + 1],      q0, xc);
                fma2(acc[16 + 2 * p + 0], q1, xa);
                fma2(acc[16 + 2 * p + 1], q1, xc);
            }
        }

        if (c + 1 < NCHUNK) {
            STS_CHUNK(b ^ 1);
            __syncthreads();
        }
    }

    // ---- write split-K partials (raw sums; scale/bias applied in reduce)
    float* P = &g_partial[blockIdx.y][0][0];
    const int o0 = ob + 2 * t;
#pragma unroll
    for (int p = 0; p < 16; p++) {
        float a0lo, a0hi, a1lo, a1hi;
        asm("mov.b64 {%0, %1}, %2;" : "=f"(a0lo), "=f"(a0hi) : "l"(acc[p]));
        asm("mov.b64 {%0, %1}, %2;" : "=f"(a1lo), "=f"(a1hi) : "l"(acc[16 + p]));
        float2 v0 = make_float2(a0lo, a1lo);     // m = 2p,   o0 / o0+1
        float2 v1 = make_float2(a0hi, a1hi);     // m = 2p+1
        *(float2*)(P + (size_t)(2 * p + 0) * OUT_DIM + o0) = v0;
        *(float2*)(P + (size_t)(2 * p + 1) * OUT_DIM + o0) = v1;
    }
}

__global__ __launch_bounds__(256)
void qgemm_reduce(const float* __restrict__ scalep,
                  const float* __restrict__ bias,
                  float* __restrict__ out)
{
    const int gid = blockIdx.x * blockDim.x + threadIdx.x;   // 0..131071
    const int idx = gid * 4;
    const int m = idx >> 14;              // OUT_DIM = 2^14
    const int o = idx & (OUT_DIM - 1);
    const float s = scalep[0];

    float4 a = make_float4(0.f, 0.f, 0.f, 0.f);
#pragma unroll
    for (int sp = 0; sp < NSPLIT; sp++) {
        float4 v = *(const float4*)&g_partial[sp][m][o];
        a.x += v.x; a.y += v.y; a.z += v.z; a.w += v.w;
    }
    float4 b4 = *(const float4*)(bias + o);
    float4 r;
    r.x = fmaf(s, a.x, b4.x);
    r.y = fmaf(s, a.y, b4.y);
    r.z = fmaf(s, a.z, b4.z);
    r.w = fmaf(s, a.w, b4.w);
    *(float4*)(out + idx) = r;
}

extern "C" void kernel_launch(void* const* d_in, const int* in_sizes, int n_in,
                              void* d_out, int out_size)
{
    const float* x     = (const float*)d_in[0];
    const int*   wq    = (const int*)  d_in[1];
    const int*   zero  = (const int*)  d_in[2];
    const float* scale = (const float*)d_in[3];
    const float* bias  = (const float*)d_in[4];
    float*       out   = (float*)d_out;

    cudaFuncSetAttribute(qgemm_main,
                         cudaFuncAttributeMaxDynamicSharedMemorySize, SMEM_BYTES);

    qgemm_main<<<dim3(OUT_DIM / OTILE, NSPLIT), 256, SMEM_BYTES>>>(x, wq, zero);
    qgemm_reduce<<<(MDIM * OUT_DIM / 4) / 256, 256>>>(scale, bias, out);
}